// round 6
// baseline (speedup 1.0000x reference)
#include <cuda_runtime.h>
#include <math.h>

// ---------------------------------------------------------------------------
// Compile-time stiffness coefficients (exact cofactor inverse of the 6x6
// compliance matrix, which is block-diagonal: asymmetric 3x3 block + 0.075*I).
// ---------------------------------------------------------------------------
constexpr double K_a = 1.0 / 0.21;          // 1/Ep
constexpr double K_b = 0.4 / 0.21;          // vp/Ep
constexpr double K_c = 0.4;                 // vp  (the asymmetry in row 2)
constexpr double K_A11 = K_a * K_a - K_b * K_c;
constexpr double K_DET = K_a * K_A11
                       - K_b * (K_b * (K_a + K_c))
                       - K_b * (K_c * (K_a + K_b));
constexpr float CM0  = (float)(K_A11 / K_DET);                      // diag(0,0)=(1,1)
constexpr float CM1  = (float)((K_b * (K_a + K_c)) / K_DET);        // (0,1)=(1,0)
constexpr float CM23 = (float)(((K_b + K_c) * (K_a + K_b)) / K_DET);// (0,2)+(2,0)
constexpr float CM4  = (float)((K_a * K_a - K_b * K_b) / K_DET);    // (2,2)
constexpr float CSH  = (float)((0.21 / 2.8) * 0.25);                // 0.075 * 0.5^2

// Reduction state (zero at module load; the finalizing block restores zeros
// every call, so the kernel stays deterministic across graph replays).
__device__ double       g_sum  = 0.0;
__device__ unsigned int g_cnt  = 0u;
__device__ unsigned int g_done = 0u;

__device__ __forceinline__ void accum_point(
    float ux, float uy, float uz,
    float vx, float vy, float vz,
    float wx, float wy, float wz,
    float sdf, float& acc, int& cnt)
{
    float e0 = ux, e1 = vy, e2 = wz;
    float s3 = uy + vx;
    float s4 = uz + wx;
    float s5 = wy + vz;
    float q = CM0 * (e0 * e0 + e1 * e1)
            + 2.0f * CM1 * (e0 * e1)
            + CM23 * ((e0 + e1) * e2)
            + CM4 * (e2 * e2)
            + CSH * (s3 * s3 + s4 * s4 + s5 * s5);
    if (sdf < 1e-8f) {
        acc += q * q;
        cnt += 1;
    }
}

__global__ void __launch_bounds__(256)
biomech_loss_kernel(const float4* __restrict__ U,
                    const float4* __restrict__ V,
                    const float4* __restrict__ W,
                    const float4* __restrict__ S,
                    const float*  __restrict__ gu,
                    const float*  __restrict__ gv,
                    const float*  __restrict__ gw,
                    const float*  __restrict__ sd,
                    float* __restrict__ out,
                    int ngroups, int n)
{
    // Per-warp staging buffer: 96 float4 = 1536 B (reused for U, V, W).
    __shared__ float4 stage[8][96];

    const int lane  = threadIdx.x & 31;
    const int wid   = threadIdx.x >> 5;
    const int gwarp = (blockIdx.x * blockDim.x + threadIdx.x) >> 5;
    const int nwarp = (gridDim.x * blockDim.x) >> 5;
    const int ntiles = ngroups >> 5;          // 32 float4-groups per warp-tile

    float4* buf = stage[wid];

    float acc = 0.0f;
    int   cnt = 0;

    for (int tile = gwarp; tile < ntiles; tile += nwarp) {
        const int g0 = tile << 5;             // first float4-group of this tile
        const float4* Ub = U + 3 * g0;
        const float4* Vb = V + 3 * g0;
        const float4* Wb = W + 3 * g0;

        // Fully coalesced loads (4 lines per LDG.128), all front-batched.
        float4 s  = __ldcs(&S[g0 + lane]);
        float4 a0 = __ldcs(&Ub[lane]);
        float4 a1 = __ldcs(&Ub[32 + lane]);
        float4 a2 = __ldcs(&Ub[64 + lane]);
        float4 b0 = __ldcs(&Vb[lane]);
        float4 b1 = __ldcs(&Vb[32 + lane]);
        float4 b2 = __ldcs(&Vb[64 + lane]);
        float4 c0 = __ldcs(&Wb[lane]);
        float4 c1 = __ldcs(&Wb[32 + lane]);
        float4 c2 = __ldcs(&Wb[64 + lane]);

        // Stage U through smem: lane l ends up with float4s 3l..3l+2
        // (48B-strided LDS.128 is bank-conflict-free: 3 coprime with 8).
        buf[lane] = a0; buf[32 + lane] = a1; buf[64 + lane] = a2;
        __syncwarp();
        float4 u0 = buf[3 * lane], u1 = buf[3 * lane + 1], u2 = buf[3 * lane + 2];
        __syncwarp();

        buf[lane] = b0; buf[32 + lane] = b1; buf[64 + lane] = b2;
        __syncwarp();
        float4 v0 = buf[3 * lane], v1 = buf[3 * lane + 1], v2 = buf[3 * lane + 2];
        __syncwarp();

        buf[lane] = c0; buf[32 + lane] = c1; buf[64 + lane] = c2;
        __syncwarp();
        float4 w0 = buf[3 * lane], w1 = buf[3 * lane + 1], w2 = buf[3 * lane + 2];
        __syncwarp();

        // Lane l now owns group g0+l (4 consecutive points) and its sdf float4.
        accum_point(u0.x, u0.y, u0.z, v0.x, v0.y, v0.z, w0.x, w0.y, w0.z, s.x, acc, cnt);
        accum_point(u0.w, u1.x, u1.y, v0.w, v1.x, v1.y, w0.w, w1.x, w1.y, s.y, acc, cnt);
        accum_point(u1.z, u1.w, u2.x, v1.z, v1.w, v2.x, w1.z, w1.w, w2.x, s.z, acc, cnt);
        accum_point(u2.y, u2.z, u2.w, v2.y, v2.z, v2.w, w2.y, w2.z, w2.w, s.w, acc, cnt);
    }

    // Tail: leftover groups (ngroups % 32) and leftover points (n % 4),
    // i.e. points [4*32*ntiles, n). At most 131 points; one thread handles it.
    if (blockIdx.x == 0 && threadIdx.x == 0) {
        for (int p = (ntiles << 5) * 4; p < n; p++) {
            accum_point(gu[3 * p], gu[3 * p + 1], gu[3 * p + 2],
                        gv[3 * p], gv[3 * p + 1], gv[3 * p + 2],
                        gw[3 * p], gw[3 * p + 1], gw[3 * p + 2],
                        sd[p], acc, cnt);
        }
    }

    // Warp reduction.
    #pragma unroll
    for (int o = 16; o > 0; o >>= 1) {
        acc += __shfl_down_sync(0xFFFFFFFFu, acc, o);
        cnt += __shfl_down_sync(0xFFFFFFFFu, cnt, o);
    }

    __shared__ float sacc[8];
    __shared__ int   scnt[8];
    if (lane == 0) { sacc[wid] = acc; scnt[wid] = cnt; }
    __syncthreads();

    if (wid == 0) {
        acc = (lane < 8) ? sacc[lane] : 0.0f;
        cnt = (lane < 8) ? scnt[lane] : 0;
        #pragma unroll
        for (int o = 4; o > 0; o >>= 1) {
            acc += __shfl_down_sync(0xFFFFFFFFu, acc, o);
            cnt += __shfl_down_sync(0xFFFFFFFFu, cnt, o);
        }
        if (lane == 0) {
            atomicAdd(&g_sum, (double)acc);
            atomicAdd(&g_cnt, (unsigned int)cnt);
            __threadfence();
            unsigned int ticket = atomicAdd(&g_done, 1u);
            if (ticket == gridDim.x - 1u) {
                // Last block: all prior atomics are visible (fence + atomic order).
                double       total = atomicAdd(&g_sum, 0.0);
                unsigned int c     = atomicAdd(&g_cnt, 0u);
                out[0] = (float)(sqrt(total) / (double)c);
                // Restore zero-state for the next (graph-replayed) call.
                g_sum  = 0.0;
                g_cnt  = 0u;
                g_done = 0u;
            }
        }
    }
}

extern "C" void kernel_launch(void* const* d_in, const int* in_sizes, int n_in,
                              void* d_out, int out_size)
{
    const float* gu = (const float*)d_in[0];
    const float* gv = (const float*)d_in[1];
    const float* gw = (const float*)d_in[2];
    const float* sd = (const float*)d_in[3];
    float* out = (float*)d_out;

    int n  = in_sizes[3];      // number of points (gt_sdf element count)
    int ng = n / 4;            // float4 groups

    // Single wave at ~4 CTAs/SM (register-limited with 10 live float4s).
    int nsm = 152;
    if (cudaDeviceGetAttribute(&nsm, cudaDevAttrMultiProcessorCount, 0)
        != cudaSuccess || nsm <= 0) {
        nsm = 152;
    }
    int blocks = 4 * nsm;
    int max_needed = ((ng >> 5) + 7) / 8;   // enough warps to cover all tiles
    if (max_needed < 1) max_needed = 1;
    if (blocks > max_needed) blocks = max_needed;

    biomech_loss_kernel<<<blocks, 256>>>(
        (const float4*)gu, (const float4*)gv, (const float4*)gw, (const float4*)sd,
        gu, gv, gw, sd, out, ng, n);
}

// round 8
// speedup vs baseline: 1.0072x; 1.0072x over previous
#include <cuda_runtime.h>
#include <math.h>

// ---------------------------------------------------------------------------
// Compile-time stiffness coefficients (exact cofactor inverse of the 6x6
// compliance matrix, which is block-diagonal: asymmetric 3x3 block + 0.075*I).
// ---------------------------------------------------------------------------
constexpr double K_a = 1.0 / 0.21;          // 1/Ep
constexpr double K_b = 0.4 / 0.21;          // vp/Ep
constexpr double K_c = 0.4;                 // vp  (the asymmetry in row 2)
constexpr double K_A11 = K_a * K_a - K_b * K_c;
constexpr double K_DET = K_a * K_A11
                       - K_b * (K_b * (K_a + K_c))
                       - K_b * (K_c * (K_a + K_b));
constexpr float CM0  = (float)(K_A11 / K_DET);                      // diag(0,0)=(1,1)
constexpr float CM1  = (float)((K_b * (K_a + K_c)) / K_DET);        // (0,1)=(1,0)
constexpr float CM23 = (float)(((K_b + K_c) * (K_a + K_b)) / K_DET);// (0,2)+(2,0)
constexpr float CM4  = (float)((K_a * K_a - K_b * K_b) / K_DET);    // (2,2)
constexpr float CSH  = (float)((0.21 / 2.8) * 0.25);                // 0.075 * 0.5^2

// Reduction state (zero at module load; the finalizing block restores zeros
// every call, so the kernel stays deterministic across graph replays).
__device__ double       g_sum  = 0.0;
__device__ unsigned int g_cnt  = 0u;
__device__ unsigned int g_done = 0u;

__device__ __forceinline__ void accum_point(
    float ux, float uy, float uz,
    float vx, float vy, float vz,
    float wx, float wy, float wz,
    float sdf, float& acc, int& cnt)
{
    float e0 = ux, e1 = vy, e2 = wz;
    float s3 = uy + vx;
    float s4 = uz + wx;
    float s5 = wy + vz;
    float q = CM0 * (e0 * e0 + e1 * e1)
            + 2.0f * CM1 * (e0 * e1)
            + CM23 * ((e0 + e1) * e2)
            + CM4 * (e2 * e2)
            + CSH * (s3 * s3 + s4 * s4 + s5 * s5);
    if (sdf < 1e-8f) {
        acc += q * q;
        cnt += 1;
    }
}

// Process one float4-group (4 points) from preloaded registers.
__device__ __forceinline__ void accum_group(
    const float4& u0, const float4& u1, const float4& u2,
    const float4& v0, const float4& v1, const float4& v2,
    const float4& w0, const float4& w1, const float4& w2,
    const float4& s, float& acc, int& cnt)
{
    accum_point(u0.x, u0.y, u0.z, v0.x, v0.y, v0.z, w0.x, w0.y, w0.z, s.x, acc, cnt);
    accum_point(u0.w, u1.x, u1.y, v0.w, v1.x, v1.y, w0.w, w1.x, w1.y, s.y, acc, cnt);
    accum_point(u1.z, u1.w, u2.x, v1.z, v1.w, v2.x, w1.z, w1.w, w2.x, s.z, acc, cnt);
    accum_point(u2.y, u2.z, u2.w, v2.y, v2.z, v2.w, w2.y, w2.z, w2.w, s.w, acc, cnt);
}

__global__ void __launch_bounds__(256)
biomech_loss_kernel(const float4* __restrict__ U,
                    const float4* __restrict__ V,
                    const float4* __restrict__ W,
                    const float4* __restrict__ S,
                    float* __restrict__ out,
                    int ngroups, int n)
{
    const int stride = gridDim.x * blockDim.x;
    float acc = 0.0f;
    int   cnt = 0;

    int t = blockIdx.x * blockDim.x + threadIdx.x;

    // 2-deep software pipeline: 20 independent LDG.128 in flight per thread,
    // then two 4-point accumulation batches.
    for (; t + stride < ngroups; t += 2 * stride) {
        const int t2 = t + stride;

        float4 sA  = __ldcs(&S[t]);
        float4 a0 = __ldcs(&U[3 * t + 0]);
        float4 a1 = __ldcs(&U[3 * t + 1]);
        float4 a2 = __ldcs(&U[3 * t + 2]);
        float4 b0 = __ldcs(&V[3 * t + 0]);
        float4 b1 = __ldcs(&V[3 * t + 1]);
        float4 b2 = __ldcs(&V[3 * t + 2]);
        float4 c0 = __ldcs(&W[3 * t + 0]);
        float4 c1 = __ldcs(&W[3 * t + 1]);
        float4 c2 = __ldcs(&W[3 * t + 2]);

        float4 sB  = __ldcs(&S[t2]);
        float4 d0 = __ldcs(&U[3 * t2 + 0]);
        float4 d1 = __ldcs(&U[3 * t2 + 1]);
        float4 d2 = __ldcs(&U[3 * t2 + 2]);
        float4 e0 = __ldcs(&V[3 * t2 + 0]);
        float4 e1 = __ldcs(&V[3 * t2 + 1]);
        float4 e2 = __ldcs(&V[3 * t2 + 2]);
        float4 f0 = __ldcs(&W[3 * t2 + 0]);
        float4 f1 = __ldcs(&W[3 * t2 + 1]);
        float4 f2 = __ldcs(&W[3 * t2 + 2]);

        accum_group(a0, a1, a2, b0, b1, b2, c0, c1, c2, sA, acc, cnt);
        accum_group(d0, d1, d2, e0, e1, e2, f0, f1, f2, sB, acc, cnt);
    }

    // Leftover single iteration (at most one per thread).
    for (; t < ngroups; t += stride) {
        float4 s  = __ldcs(&S[t]);
        float4 a0 = __ldcs(&U[3 * t + 0]);
        float4 a1 = __ldcs(&U[3 * t + 1]);
        float4 a2 = __ldcs(&U[3 * t + 2]);
        float4 b0 = __ldcs(&V[3 * t + 0]);
        float4 b1 = __ldcs(&V[3 * t + 1]);
        float4 b2 = __ldcs(&V[3 * t + 2]);
        float4 c0 = __ldcs(&W[3 * t + 0]);
        float4 c1 = __ldcs(&W[3 * t + 1]);
        float4 c2 = __ldcs(&W[3 * t + 2]);
        accum_group(a0, a1, a2, b0, b1, b2, c0, c1, c2, s, acc, cnt);
    }

    // Scalar tail (N % 4 != 0): one thread, scalar views of the same buffers.
    if (blockIdx.x == 0 && threadIdx.x == 0) {
        const float* gu = (const float*)U;
        const float* gv = (const float*)V;
        const float* gw = (const float*)W;
        const float* sd = (const float*)S;
        for (int p = 4 * ngroups; p < n; p++) {
            accum_point(gu[3 * p], gu[3 * p + 1], gu[3 * p + 2],
                        gv[3 * p], gv[3 * p + 1], gv[3 * p + 2],
                        gw[3 * p], gw[3 * p + 1], gw[3 * p + 2],
                        sd[p], acc, cnt);
        }
    }

    // Warp reduction.
    #pragma unroll
    for (int o = 16; o > 0; o >>= 1) {
        acc += __shfl_down_sync(0xFFFFFFFFu, acc, o);
        cnt += __shfl_down_sync(0xFFFFFFFFu, cnt, o);
    }

    __shared__ float sacc[8];
    __shared__ int   scnt[8];
    int wid  = threadIdx.x >> 5;
    int lane = threadIdx.x & 31;
    if (lane == 0) { sacc[wid] = acc; scnt[wid] = cnt; }
    __syncthreads();

    if (wid == 0) {
        acc = (lane < 8) ? sacc[lane] : 0.0f;
        cnt = (lane < 8) ? scnt[lane] : 0;
        #pragma unroll
        for (int o = 4; o > 0; o >>= 1) {
            acc += __shfl_down_sync(0xFFFFFFFFu, acc, o);
            cnt += __shfl_down_sync(0xFFFFFFFFu, cnt, o);
        }
        if (lane == 0) {
            atomicAdd(&g_sum, (double)acc);
            atomicAdd(&g_cnt, (unsigned int)cnt);
            __threadfence();
            unsigned int ticket = atomicAdd(&g_done, 1u);
            if (ticket == gridDim.x - 1u) {
                // Last block: all prior atomics are visible (fence + atomic order).
                double       total = atomicAdd(&g_sum, 0.0);
                unsigned int c     = atomicAdd(&g_cnt, 0u);
                out[0] = (float)(sqrt(total) / (double)c);
                // Restore zero-state for the next (graph-replayed) call.
                g_sum  = 0.0;
                g_cnt  = 0u;
                g_done = 0u;
            }
        }
    }
}

extern "C" void kernel_launch(void* const* d_in, const int* in_sizes, int n_in,
                              void* d_out, int out_size)
{
    const float* gu = (const float*)d_in[0];
    const float* gv = (const float*)d_in[1];
    const float* gw = (const float*)d_in[2];
    const float* sd = (const float*)d_in[3];
    float* out = (float*)d_out;

    int n  = in_sizes[3];      // number of points (gt_sdf element count)
    int ng = n / 4;            // float4 groups

    // Size the persistent grid to exactly one resident wave, from the
    // actual register usage (queried, not guessed).
    int nsm = 152;
    if (cudaDeviceGetAttribute(&nsm, cudaDevAttrMultiProcessorCount, 0)
        != cudaSuccess || nsm <= 0) {
        nsm = 152;
    }
    int ctas_per_sm = 2;
    cudaFuncAttributes fa;
    if (cudaFuncGetAttributes(&fa, (const void*)biomech_loss_kernel)
        == cudaSuccess && fa.numRegs > 0) {
        ctas_per_sm = 65536 / (fa.numRegs * 256);
        if (ctas_per_sm < 1) ctas_per_sm = 1;
        if (ctas_per_sm > 8) ctas_per_sm = 8;   // 64-warp/SM cap at 256 thr
    }
    int blocks = ctas_per_sm * nsm;
    int max_needed = (ng + 255) / 256;
    if (blocks > max_needed) blocks = max_needed;
    if (blocks < 1) blocks = 1;

    biomech_loss_kernel<<<blocks, 256>>>(
        (const float4*)gu, (const float4*)gv, (const float4*)gw, (const float4*)sd,
        out, ng, n);
}